// round 8
// baseline (speedup 1.0000x reference)
#include <cuda_runtime.h>
#include <cuda_bf16.h>
#include <math.h>

// Problem constants
#define BATCH   16
#define HEADS   16
#define T_NEW   8
#define T_PAST  4096
#define T_FULL  4104
#define HD      64
#define CDIM    1024
#define M_ROWS  128          // B*T_new
#define QKV_N   3072

#define ATILE   128          // keys per tile
#define NSPLIT  4            // KV splits
#define SPAD    132          // S_s row stride
#define VPAD    72           // v_s row stride (halves at +0 / +36)

// Scratch (device globals; no allocations allowed)
__device__ float  g_qkv[M_ROWS * QKV_N];
__device__ float  g_y[M_ROWS * CDIM];
__device__ float  g_py[NSPLIT * 256 * T_NEW * HD];
__device__ float2 g_ml[NSPLIT * 256 * T_NEW];

// ---------------------------------------------------------------------------
// fp32 GEMM: C = A @ W^T + b. BK=32, 1 row x 4 cols per thread, NT=BM*BN/4.
// mode 1: C := g_qkv. mode 2: A := g_y.
// ---------------------------------------------------------------------------
template<int BM, int BN, int BK, int NT>
__global__ void __launch_bounds__(NT) gemm_bias_t(
    const float* __restrict__ Ap, const float* __restrict__ W,
    const float* __restrict__ bias, float* __restrict__ Cp,
    int M, int N, int K, int mode)
{
    const float* A = (mode == 2) ? g_y : Ap;
    float* C = (mode == 1) ? g_qkv : Cp;

    __shared__ float a_s[BK][BM + 4];
    __shared__ float b_s[BK][BN + 4];

    const int tid = threadIdx.x;
    const int m0 = blockIdx.y * BM;
    const int n0 = blockIdx.x * BN;
    const int tx = tid % (BN / 4);
    const int ty = tid / (BN / 4);   // 0..BM-1

    float acc[4] = {0.f, 0.f, 0.f, 0.f};

    for (int k0 = 0; k0 < K; k0 += BK) {
#pragma unroll
        for (int i = tid; i < BM * BK / 4; i += NT) {
            const int r = i / (BK / 4), c4 = i % (BK / 4);
            const float4 v = *(const float4*)&A[(size_t)(m0 + r) * K + k0 + 4 * c4];
            a_s[4 * c4 + 0][r] = v.x; a_s[4 * c4 + 1][r] = v.y;
            a_s[4 * c4 + 2][r] = v.z; a_s[4 * c4 + 3][r] = v.w;
        }
#pragma unroll
        for (int i = tid; i < BN * BK / 4; i += NT) {
            const int r = i / (BK / 4), c4 = i % (BK / 4);
            const float4 v = *(const float4*)&W[(size_t)(n0 + r) * K + k0 + 4 * c4];
            b_s[4 * c4 + 0][r] = v.x; b_s[4 * c4 + 1][r] = v.y;
            b_s[4 * c4 + 2][r] = v.z; b_s[4 * c4 + 3][r] = v.w;
        }
        __syncthreads();
#pragma unroll
        for (int kk = 0; kk < BK; kk++) {
            const float a = a_s[kk][ty];
            const float4 bv = *(const float4*)&b_s[kk][tx * 4];
            acc[0] += a * bv.x; acc[1] += a * bv.y;
            acc[2] += a * bv.z; acc[3] += a * bv.w;
        }
        __syncthreads();
    }
    const float4 bb = *(const float4*)&bias[n0 + tx * 4];
    *(float4*)&C[(size_t)(m0 + ty) * N + n0 + tx * 4] =
        make_float4(acc[0] + bb.x, acc[1] + bb.y, acc[2] + bb.z, acc[3] + bb.w);
}

// ---------------------------------------------------------------------------
// Fused attention + KV-cache copy, split-KV, coalesced, 3 blocks/SM.
// Grid (256, 4). 256 threads, 8 warps. Warp w owns rows [16w,16w+16) of each
// 128-key tile; instruction covers 2 rows (lane = 16B chunk, rh = row half):
// every LDG/STG.128 is 512B contiguous. One row-pair in flight (low regs).
// Scores: butterfly-fold partials over 16 dim-lanes (15 shfl); lane qi=lane&7.
// PV: warp w owns dims [8w,8w+8); lane=(qi=lane&7, jg=lane>>3).
// ---------------------------------------------------------------------------
__global__ void __launch_bounds__(256, 3) attn_fused_kernel(
    const float* __restrict__ past_k, const float* __restrict__ past_v,
    float* __restrict__ out_k, float* __restrict__ out_v)
{
    __shared__ float q_s[T_NEW * HD];
    __shared__ float S_s[T_NEW * SPAD];
    __shared__ float v_s[ATILE * VPAD];   // row r: dims 0-31 at +0, 32-63 at +36
    __shared__ float f_s[T_NEW];

    const int bh = blockIdx.x;
    const int split = blockIdx.y;
    const int b = bh >> 4;
    const int h = bh & 15;
    const int tid = threadIdx.x;
    const int lane = tid & 31;
    const int w = tid >> 5;

    const int dg = lane & 15;    // 16B dim-chunk (dims 4dg..4dg+3)
    const int rh = lane >> 4;    // row half within instruction

    const int pqi = lane & 7;    // PV/score: query owned by this lane
    const int jg  = lane >> 3;   // PV: j subgroup
    const int voff = w * 8 + ((w >= 4) ? 4 : 0);

    // stage q to smem, then per-lane regs (dims 4dg..4dg+3 of each query)
    for (int idx = tid; idx < T_NEW * HD; idx += 256) {
        const int qq = idx >> 6, d = idx & 63;
        q_s[idx] = g_qkv[(size_t)(b * T_NEW + qq) * QKV_N + h * HD + d] * 0.125f;
    }
    __syncthreads();
    float4 qr[8];
#pragma unroll
    for (int qi = 0; qi < 8; qi++)
        qr[qi] = *(const float4*)&q_s[qi * HD + 4 * dg];

    float m = -INFINITY, l = 0.f;
    float acc[8];
#pragma unroll
    for (int d = 0; d < 8; d++) acc[d] = 0.f;

    const int tmax = (split == NSPLIT - 1) ? 9 : 8;

    for (int t = 0; t < tmax; t++) {
        const int nk = (t < 8) ? ATILE : T_NEW;
        const int tilebase = split * 1024 + t * ATILE;

        // --- K/V rows: one pair in flight; load -> copy-out -> score ---
#pragma unroll
        for (int i = 0; i < 8; i++) {
            const int r = 16 * w + 2 * i + rh;
            const int kt = tilebase + r;
            float4 kr, vr;
            if (r < nk) {
                if (kt < T_PAST) {
                    kr = __ldcs((const float4*)
                        (past_k + ((size_t)bh * T_PAST + kt) * HD + 4 * dg));
                    vr = __ldcs((const float4*)
                        (past_v + ((size_t)bh * T_PAST + kt) * HD + 4 * dg));
                } else {
                    const size_t nb = (size_t)(b * T_NEW + (kt - T_PAST)) * QKV_N
                                      + h * HD + 4 * dg;
                    kr = *(const float4*)(g_qkv + nb + CDIM);
                    vr = *(const float4*)(g_qkv + nb + 2 * CDIM);
                }
                // fused cache copy-out (coalesced, streaming)
                __stcs((float4*)&out_k[((size_t)bh * T_FULL + kt) * HD + 4 * dg], kr);
                __stcs((float4*)&out_v[((size_t)bh * T_FULL + kt) * HD + 4 * dg], vr);
                // V into smem (conflict-free: stride 72, halves at +0/+36)
                *(float4*)&v_s[r * VPAD + 4 * dg + ((dg >= 8) ? 4 : 0)] = vr;
            } else {
                kr = make_float4(0.f, 0.f, 0.f, 0.f);
            }

            // scores: butterfly-fold partials over the 16 dim-lanes
            float p[8];
#pragma unroll
            for (int qi = 0; qi < 8; qi++)
                p[qi] = qr[qi].x * kr.x + qr[qi].y * kr.y
                      + qr[qi].z * kr.z + qr[qi].w * kr.w;
#pragma unroll
            for (int qi = 0; qi < 8; qi++)
                p[qi] += __shfl_xor_sync(0xffffffffu, p[qi], 8);
#pragma unroll
            for (int q = 0; q < 4; q++) {
                const float send = (lane & 4) ? p[q] : p[q + 4];
                const float got = __shfl_xor_sync(0xffffffffu, send, 4);
                p[q] = ((lane & 4) ? p[q + 4] : p[q]) + got;
            }
#pragma unroll
            for (int q = 0; q < 2; q++) {
                const float send = (lane & 2) ? p[q] : p[q + 2];
                const float got = __shfl_xor_sync(0xffffffffu, send, 2);
                p[q] = ((lane & 2) ? p[q + 2] : p[q]) + got;
            }
            {
                const float send = (lane & 1) ? p[0] : p[1];
                const float got = __shfl_xor_sync(0xffffffffu, send, 1);
                p[0] = ((lane & 1) ? p[1] : p[0]) + got;
            }
            // lane holds s(row = 16w+2i+(lane>>4), qi = lane&7)
            if ((lane & 8) == 0) {
                const int r2 = 16 * w + 2 * i + (lane >> 4);
                const int kt2 = tilebase + r2;
                float sv = p[0];
                if (r2 >= nk) sv = -INFINITY;
                else if (kt2 >= T_PAST && pqi < (kt2 - T_PAST)) sv = -INFINITY;
                S_s[pqi * SPAD + r2] = sv;
            }
        }
        __syncthreads();

        // --- online softmax: warp w owns query w ---
        float pr[4];
        float lmax = -INFINITY;
#pragma unroll
        for (int k = 0; k < 4; k++) {
            pr[k] = S_s[w * SPAD + lane + 32 * k];
            lmax = fmaxf(lmax, pr[k]);
        }
#pragma unroll
        for (int off = 16; off; off >>= 1)
            lmax = fmaxf(lmax, __shfl_xor_sync(0xffffffffu, lmax, off));
        const float m_new = fmaxf(m, lmax);
        const float factor = __expf(m - m_new);
        float psum = 0.f;
#pragma unroll
        for (int k = 0; k < 4; k++) {
            const float e = __expf(pr[k] - m_new);
            psum += e;
            S_s[w * SPAD + lane + 32 * k] = e;
        }
#pragma unroll
        for (int off = 16; off; off >>= 1)
            psum += __shfl_xor_sync(0xffffffffu, psum, off);
        l = l * factor + psum;
        m = m_new;
        if (lane == 0) f_s[w] = factor;
        __syncthreads();

        // --- PV: warp w covers dims [8w,8w+8); lane = (pqi, jg) ---
        {
            const float fct = f_s[pqi];
#pragma unroll
            for (int d = 0; d < 8; d++) acc[d] *= fct;
            const float* vrow = v_s + voff;
#pragma unroll 4
            for (int jb = 0; jb < 32; jb++) {
                const int j = jb * 4 + jg;
                const float p = S_s[pqi * SPAD + j];
                const float4 va = *(const float4*)&vrow[j * VPAD];
                const float4 vb = *(const float4*)&vrow[j * VPAD + 4];
                acc[0] += p * va.x; acc[1] += p * va.y;
                acc[2] += p * va.z; acc[3] += p * va.w;
                acc[4] += p * vb.x; acc[5] += p * vb.y;
                acc[6] += p * vb.z; acc[7] += p * vb.w;
            }
        }
        __syncthreads();
    }

    // reduce over jg (xor 8, 16) — warp-uniform
#pragma unroll
    for (int d = 0; d < 8; d++) {
        acc[d] += __shfl_xor_sync(0xffffffffu, acc[d], 8);
        acc[d] += __shfl_xor_sync(0xffffffffu, acc[d], 16);
    }
    if (lane < 8) {
        const size_t base = ((size_t)(split * 256 + bh) * T_NEW + lane) * HD + w * 8;
        *(float4*)&g_py[base]     = make_float4(acc[0], acc[1], acc[2], acc[3]);
        *(float4*)&g_py[base + 4] = make_float4(acc[4], acc[5], acc[6], acc[7]);
    }
    if (lane == 0)
        g_ml[(split * 256 + bh) * T_NEW + w] = make_float2(m, l);
}

// ---------------------------------------------------------------------------
// Combine split partials -> g_y. Grid 256 (bh), 256 threads.
// ---------------------------------------------------------------------------
__global__ void __launch_bounds__(256) combine_kernel()
{
    const int bh = blockIdx.x;
    const int b = bh >> 4;
    const int h = bh & 15;
    const int tid = threadIdx.x;
    const int qi = tid >> 5;
    const int dd = (tid & 31) * 2;

    float2 ml[NSPLIT];
    float M = -INFINITY;
#pragma unroll
    for (int s = 0; s < NSPLIT; s++) {
        ml[s] = g_ml[(s * 256 + bh) * T_NEW + qi];
        M = fmaxf(M, ml[s].x);
    }
    float lt = 0.f, y0 = 0.f, y1 = 0.f;
#pragma unroll
    for (int s = 0; s < NSPLIT; s++) {
        const float wt = __expf(ml[s].x - M);
        lt += ml[s].y * wt;
        const float2 yv = *(const float2*)
            &g_py[((size_t)(s * 256 + bh) * T_NEW + qi) * HD + dd];
        y0 += yv.x * wt;
        y1 += yv.y * wt;
    }
    const float inv = 1.f / lt;
    *(float2*)&g_y[(size_t)(b * T_NEW + qi) * CDIM + h * HD + dd] =
        make_float2(y0 * inv, y1 * inv);
}

// ---------------------------------------------------------------------------
// Launcher — ONLY kernel launches.
// Output layout: [ out (128*1024) | k (256*4104*64) | v (256*4104*64) ]
// ---------------------------------------------------------------------------
extern "C" void kernel_launch(void* const* d_in, const int* in_sizes, int n_in,
                              void* d_out, int out_size)
{
    const float* x      = (const float*)d_in[0];
    const float* past_k = (const float*)d_in[1];
    const float* past_v = (const float*)d_in[2];
    const float* W_attn = (const float*)d_in[3];
    const float* b_attn = (const float*)d_in[4];
    const float* W_proj = (const float*)d_in[5];
    const float* b_proj = (const float*)d_in[6];

    float* out   = (float*)d_out;
    float* out_k = out + (size_t)M_ROWS * CDIM;
    float* out_v = out_k + (size_t)BATCH * HEADS * T_FULL * HD;

    // 1) QKV projection -> g_qkv  (384 blocks)
    {
        dim3 grid(QKV_N / 64, M_ROWS / 16);
        gemm_bias_t<16, 64, 32, 256><<<grid, 256>>>(x, W_attn, b_attn, nullptr,
                                                    M_ROWS, QKV_N, CDIM, 1);
    }

    // 2) Fused attention + KV-cache copy (split-KV, 1024 blocks, 3/SM)
    {
        dim3 grid(BATCH * HEADS, NSPLIT);
        attn_fused_kernel<<<grid, 256>>>(past_k, past_v, out_k, out_v);
    }

    // 3) Combine split partials -> g_y
    combine_kernel<<<BATCH * HEADS, 256>>>();

    // 4) Output projection -> out  (128 blocks)
    {
        dim3 grid(CDIM / 64, M_ROWS / 16);
        gemm_bias_t<16, 64, 32, 256><<<grid, 256>>>(nullptr, W_proj, b_proj, out,
                                                    M_ROWS, CDIM, CDIM, 2);
    }
}

// round 10
// speedup vs baseline: 1.4924x; 1.4924x over previous
#include <cuda_runtime.h>
#include <cuda_bf16.h>
#include <math.h>

// Problem constants
#define BATCH   16
#define HEADS   16
#define T_NEW   8
#define T_PAST  4096
#define T_FULL  4104
#define HD      64
#define CDIM    1024
#define M_ROWS  128          // B*T_new
#define QKV_N   3072

#define ATILE   128          // keys per tile
#define NSPLIT  4            // KV splits
#define SPAD    132          // S_s row stride
#define VPAD    72           // v_s row stride (halves at +0 / +36)
#define KSPLIT  4            // GEMM split-K factor

// Scratch (device globals; no allocations allowed)
__device__ float  g_qkv[M_ROWS * QKV_N];
__device__ float  g_y[M_ROWS * CDIM];
__device__ float  g_py[NSPLIT * 256 * T_NEW * HD];
__device__ float2 g_ml[NSPLIT * 256 * T_NEW];
__device__ float  g_gp[KSPLIT * M_ROWS * QKV_N];   // 6MB QKV split-K partials
__device__ float  g_pp[KSPLIT * M_ROWS * CDIM];    // 2MB proj split-K partials

// ---------------------------------------------------------------------------
// Split-K fp32 GEMM partial: P[z] = A[:, zK/S:(z+1)K/S] @ W[:, same]^T
// BM=BN=64, BK=16, 256 threads, 4x4 microtile.
// mode 1: A := Ap, P := g_gp.  mode 2: A := g_y, P := g_pp.
// Grid (N/64, M/64, KSPLIT).
// ---------------------------------------------------------------------------
__global__ void __launch_bounds__(256) gemm_splitk_kernel(
    const float* __restrict__ Ap, const float* __restrict__ W,
    int M, int N, int K, int mode)
{
    const float* A = (mode == 2) ? g_y : Ap;
    float* P = (mode == 1) ? g_gp : g_pp;      // FIX: was nullptr parameter

    __shared__ float a_s[16][68];
    __shared__ float b_s[16][68];

    const int tid = threadIdx.x;
    const int m0 = blockIdx.y * 64;
    const int n0 = blockIdx.x * 64;
    const int kz = blockIdx.z;
    const int kchunk = K / KSPLIT;
    const int kbeg = kz * kchunk;

    const int tx = tid & 15;     // n sub (4 cols)
    const int ty = tid >> 4;     // m sub (4 rows)

    const int lr = tid >> 2;     // load row 0..63
    const int lc = tid & 3;      // load col-quad 0..3

    float acc[4][4];
#pragma unroll
    for (int i = 0; i < 4; i++)
#pragma unroll
        for (int j = 0; j < 4; j++) acc[i][j] = 0.f;

    for (int k0 = kbeg; k0 < kbeg + kchunk; k0 += 16) {
        {
            const float4 v = *(const float4*)&A[(size_t)(m0 + lr) * K + k0 + 4 * lc];
            a_s[4 * lc + 0][lr] = v.x; a_s[4 * lc + 1][lr] = v.y;
            a_s[4 * lc + 2][lr] = v.z; a_s[4 * lc + 3][lr] = v.w;
        }
        {
            const float4 v = *(const float4*)&W[(size_t)(n0 + lr) * K + k0 + 4 * lc];
            b_s[4 * lc + 0][lr] = v.x; b_s[4 * lc + 1][lr] = v.y;
            b_s[4 * lc + 2][lr] = v.z; b_s[4 * lc + 3][lr] = v.w;
        }
        __syncthreads();
#pragma unroll
        for (int kk = 0; kk < 16; kk++) {
            const float4 av = *(const float4*)&a_s[kk][ty * 4];
            const float4 bv = *(const float4*)&b_s[kk][tx * 4];
            const float am[4] = {av.x, av.y, av.z, av.w};
            const float bn[4] = {bv.x, bv.y, bv.z, bv.w};
#pragma unroll
            for (int i = 0; i < 4; i++)
#pragma unroll
                for (int j = 0; j < 4; j++) acc[i][j] += am[i] * bn[j];
        }
        __syncthreads();
    }

#pragma unroll
    for (int i = 0; i < 4; i++) {
        const size_t row = (size_t)kz * M + m0 + ty * 4 + i;
        *(float4*)&P[row * N + n0 + tx * 4] =
            make_float4(acc[i][0], acc[i][1], acc[i][2], acc[i][3]);
    }
}

// ---------------------------------------------------------------------------
// Reduce split-K partials + bias. One float4 per thread.
// mode 1: g_gp -> g_qkv (N=3072). mode 2: g_pp -> Cp (N=1024).
// ---------------------------------------------------------------------------
__global__ void __launch_bounds__(256) reduce_splitk_kernel(
    const float* __restrict__ bias, float* __restrict__ Cp, int N, int mode)
{
    const int idx = blockIdx.x * 256 + threadIdx.x;   // float4 index
    const float* P = (mode == 1) ? g_gp : g_pp;
    float* C = (mode == 1) ? g_qkv : Cp;
    const int total = M_ROWS * N / 4;
    if (idx >= total) return;

    const int col = (idx * 4) % N;
    float4 s = make_float4(0.f, 0.f, 0.f, 0.f);
#pragma unroll
    for (int z = 0; z < KSPLIT; z++) {
        const float4 v = *(const float4*)&P[(size_t)z * M_ROWS * N + idx * 4];
        s.x += v.x; s.y += v.y; s.z += v.z; s.w += v.w;
    }
    const float4 bb = *(const float4*)&bias[col];
    *(float4*)&C[(size_t)idx * 4] =
        make_float4(s.x + bb.x, s.y + bb.y, s.z + bb.z, s.w + bb.w);
}

// ---------------------------------------------------------------------------
// Fused attention + KV-cache copy, split-KV, fully coalesced (R6 structure:
// batched loads for high MLP). Grid (256, 4). 256 threads, 8 warps.
// Warp w owns rows [16w,16w+16); instruction covers 2 rows (lane = 16B chunk,
// rh = row half): every LDG/STG.128 is 512B contiguous.
// Scores: butterfly-fold partials over 16 dim-lanes; lane ends with qi=lane&7.
// PV: warp w owns dims [8w,8w+8); lane=(qi=lane&7, jg=lane>>3).
// ---------------------------------------------------------------------------
__global__ void __launch_bounds__(256, 2) attn_fused_kernel(
    const float* __restrict__ past_k, const float* __restrict__ past_v,
    float* __restrict__ out_k, float* __restrict__ out_v)
{
    __shared__ float q_s[T_NEW * HD];
    __shared__ float S_s[T_NEW * SPAD];
    __shared__ float v_s[ATILE * VPAD];   // row r: dims 0-31 at +0, 32-63 at +36
    __shared__ float f_s[T_NEW];

    const int bh = blockIdx.x;
    const int split = blockIdx.y;
    const int b = bh >> 4;
    const int h = bh & 15;
    const int tid = threadIdx.x;
    const int lane = tid & 31;
    const int w = tid >> 5;

    const int dg = lane & 15;    // 16B dim-chunk (dims 4dg..4dg+3)
    const int rh = lane >> 4;    // row half within instruction

    const int pqi = lane & 7;    // PV/score: query owned by this lane
    const int jg  = lane >> 3;   // PV: j subgroup
    const int voff = w * 8 + ((w >= 4) ? 4 : 0);

    // stage q to smem, then per-lane regs (dims 4dg..4dg+3 of each query)
    for (int idx = tid; idx < T_NEW * HD; idx += 256) {
        const int qq = idx >> 6, d = idx & 63;
        q_s[idx] = g_qkv[(size_t)(b * T_NEW + qq) * QKV_N + h * HD + d] * 0.125f;
    }
    __syncthreads();
    float4 qr[8];
#pragma unroll
    for (int qi = 0; qi < 8; qi++)
        qr[qi] = *(const float4*)&q_s[qi * HD + 4 * dg];

    float m = -INFINITY, l = 0.f;
    float acc[8];
#pragma unroll
    for (int d = 0; d < 8; d++) acc[d] = 0.f;

    const int tmax = (split == NSPLIT - 1) ? 9 : 8;

    for (int t = 0; t < tmax; t++) {
        const int nk = (t < 8) ? ATILE : T_NEW;
        const int tilebase = split * 1024 + t * ATILE;

        // --- batched load of K and V rows (high MLP, coalesced 512B) ---
        float4 kr[8], vr[8];
#pragma unroll
        for (int i = 0; i < 8; i++) {
            const int r = 16 * w + 2 * i + rh;
            const int kt = tilebase + r;
            if (r < nk) {
                const float* ks;
                const float* vs;
                if (kt < T_PAST) {
                    ks = past_k + ((size_t)bh * T_PAST + kt) * HD + 4 * dg;
                    vs = past_v + ((size_t)bh * T_PAST + kt) * HD + 4 * dg;
                } else {
                    const size_t nb = (size_t)(b * T_NEW + (kt - T_PAST)) * QKV_N
                                      + h * HD + 4 * dg;
                    ks = g_qkv + nb + CDIM;
                    vs = g_qkv + nb + 2 * CDIM;
                }
                kr[i] = *(const float4*)ks;
                vr[i] = *(const float4*)vs;
            } else {
                kr[i] = make_float4(0.f, 0.f, 0.f, 0.f);
                vr[i] = make_float4(0.f, 0.f, 0.f, 0.f);
            }
        }
        // --- fused cache copy-out (coalesced, streaming stores) ---
#pragma unroll
        for (int i = 0; i < 8; i++) {
            const int r = 16 * w + 2 * i + rh;
            const int kt = tilebase + r;
            if (r < nk) {
                __stcs((float4*)&out_k[((size_t)bh * T_FULL + kt) * HD + 4 * dg], kr[i]);
                __stcs((float4*)&out_v[((size_t)bh * T_FULL + kt) * HD + 4 * dg], vr[i]);
                // V into smem (conflict-free: stride 72, halves at +0/+36)
                *(float4*)&v_s[r * VPAD + 4 * dg + ((dg >= 8) ? 4 : 0)] = vr[i];
            }
        }

        // --- scores: butterfly-fold partials over the 16 dim-lanes ---
#pragma unroll
        for (int i = 0; i < 8; i++) {
            float p[8];
#pragma unroll
            for (int qi = 0; qi < 8; qi++)
                p[qi] = qr[qi].x * kr[i].x + qr[qi].y * kr[i].y
                      + qr[qi].z * kr[i].z + qr[qi].w * kr[i].w;
#pragma unroll
            for (int qi = 0; qi < 8; qi++)
                p[qi] += __shfl_xor_sync(0xffffffffu, p[qi], 8);
#pragma unroll
            for (int q = 0; q < 4; q++) {
                const float send = (lane & 4) ? p[q] : p[q + 4];
                const float got = __shfl_xor_sync(0xffffffffu, send, 4);
                p[q] = ((lane & 4) ? p[q + 4] : p[q]) + got;
            }
#pragma unroll
            for (int q = 0; q < 2; q++) {
                const float send = (lane & 2) ? p[q] : p[q + 2];
                const float got = __shfl_xor_sync(0xffffffffu, send, 2);
                p[q] = ((lane & 2) ? p[q + 2] : p[q]) + got;
            }
            {
                const float send = (lane & 1) ? p[0] : p[1];
                const float got = __shfl_xor_sync(0xffffffffu, send, 1);
                p[0] = ((lane & 1) ? p[1] : p[0]) + got;
            }
            // lane holds s(row = 16w+2i+(lane>>4), qi = lane&7)
            if ((lane & 8) == 0) {
                const int r2 = 16 * w + 2 * i + (lane >> 4);
                const int kt2 = tilebase + r2;
                float sv = p[0];
                if (r2 >= nk) sv = -INFINITY;
                else if (kt2 >= T_PAST && pqi < (kt2 - T_PAST)) sv = -INFINITY;
                S_s[pqi * SPAD + r2] = sv;
            }
        }
        __syncthreads();

        // --- online softmax: warp w owns query w ---
        float pr[4];
        float lmax = -INFINITY;
#pragma unroll
        for (int k = 0; k < 4; k++) {
            pr[k] = S_s[w * SPAD + lane + 32 * k];
            lmax = fmaxf(lmax, pr[k]);
        }
#pragma unroll
        for (int off = 16; off; off >>= 1)
            lmax = fmaxf(lmax, __shfl_xor_sync(0xffffffffu, lmax, off));
        const float m_new = fmaxf(m, lmax);
        const float factor = __expf(m - m_new);
        float psum = 0.f;
#pragma unroll
        for (int k = 0; k < 4; k++) {
            const float e = __expf(pr[k] - m_new);
            psum += e;
            S_s[w * SPAD + lane + 32 * k] = e;
        }
#pragma unroll
        for (int off = 16; off; off >>= 1)
            psum += __shfl_xor_sync(0xffffffffu, psum, off);
        l = l * factor + psum;
        m = m_new;
        if (lane == 0) f_s[w] = factor;
        __syncthreads();

        // --- PV: warp w covers dims [8w,8w+8); lane = (pqi, jg) ---
        {
            const float fct = f_s[pqi];
#pragma unroll
            for (int d = 0; d < 8; d++) acc[d] *= fct;
            const float* vrow = v_s + voff;
#pragma unroll 4
            for (int jb = 0; jb < 32; jb++) {
                const int j = jb * 4 + jg;
                const float p = S_s[pqi * SPAD + j];
                const float4 va = *(const float4*)&vrow[j * VPAD];
                const float4 vb = *(const float4*)&vrow[j * VPAD + 4];
                acc[0] += p * va.x; acc[1] += p * va.y;
                acc[2] += p * va.z; acc[3] += p * va.w;
                acc[4] += p * vb.x; acc[5] += p * vb.y;
                acc[6] += p * vb.z; acc[7] += p * vb.w;
            }
        }
        __syncthreads();
    }

    // reduce over jg (xor 8, 16) — warp-uniform
#pragma unroll
    for (int d = 0; d < 8; d++) {
        acc[d] += __shfl_xor_sync(0xffffffffu, acc[d], 8);
        acc[d] += __shfl_xor_sync(0xffffffffu, acc[d], 16);
    }
    if (lane < 8) {
        const size_t base = ((size_t)(split * 256 + bh) * T_NEW + lane) * HD + w * 8;
        *(float4*)&g_py[base]     = make_float4(acc[0], acc[1], acc[2], acc[3]);
        *(float4*)&g_py[base + 4] = make_float4(acc[4], acc[5], acc[6], acc[7]);
    }
    if (lane == 0)
        g_ml[(split * 256 + bh) * T_NEW + w] = make_float2(m, l);
}

// ---------------------------------------------------------------------------
// Combine split partials -> g_y. Grid 256 (bh), 256 threads.
// ---------------------------------------------------------------------------
__global__ void __launch_bounds__(256) combine_kernel()
{
    const int bh = blockIdx.x;
    const int b = bh >> 4;
    const int h = bh & 15;
    const int tid = threadIdx.x;
    const int qi = tid >> 5;
    const int dd = (tid & 31) * 2;

    float2 ml[NSPLIT];
    float M = -INFINITY;
#pragma unroll
    for (int s = 0; s < NSPLIT; s++) {
        ml[s] = g_ml[(s * 256 + bh) * T_NEW + qi];
        M = fmaxf(M, ml[s].x);
    }
    float lt = 0.f, y0 = 0.f, y1 = 0.f;
#pragma unroll
    for (int s = 0; s < NSPLIT; s++) {
        const float wt = __expf(ml[s].x - M);
        lt += ml[s].y * wt;
        const float2 yv = *(const float2*)
            &g_py[((size_t)(s * 256 + bh) * T_NEW + qi) * HD + dd];
        y0 += yv.x * wt;
        y1 += yv.y * wt;
    }
    const float inv = 1.f / lt;
    *(float2*)&g_y[(size_t)(b * T_NEW + qi) * CDIM + h * HD + dd] =
        make_float2(y0 * inv, y1 * inv);
}

// ---------------------------------------------------------------------------
// Launcher — ONLY kernel launches.
// Output layout: [ out (128*1024) | k (256*4104*64) | v (256*4104*64) ]
// ---------------------------------------------------------------------------
extern "C" void kernel_launch(void* const* d_in, const int* in_sizes, int n_in,
                              void* d_out, int out_size)
{
    const float* x      = (const float*)d_in[0];
    const float* past_k = (const float*)d_in[1];
    const float* past_v = (const float*)d_in[2];
    const float* W_attn = (const float*)d_in[3];
    const float* b_attn = (const float*)d_in[4];
    const float* W_proj = (const float*)d_in[5];
    const float* b_proj = (const float*)d_in[6];

    float* out   = (float*)d_out;
    float* out_k = out + (size_t)M_ROWS * CDIM;
    float* out_v = out_k + (size_t)BATCH * HEADS * T_FULL * HD;

    // 1) QKV projection partials (384 blocks) + reduce -> g_qkv
    {
        dim3 grid(QKV_N / 64, M_ROWS / 64, KSPLIT);
        gemm_splitk_kernel<<<grid, 256>>>(x, W_attn, M_ROWS, QKV_N, CDIM, 1);
        reduce_splitk_kernel<<<(M_ROWS * QKV_N / 4 + 255) / 256, 256>>>(
            b_attn, nullptr, QKV_N, 1);
    }

    // 2) Fused attention + KV-cache copy (split-KV, 1024 blocks)
    {
        dim3 grid(BATCH * HEADS, NSPLIT);
        attn_fused_kernel<<<grid, 256>>>(past_k, past_v, out_k, out_v);
    }

    // 3) Combine split partials -> g_y
    combine_kernel<<<BATCH * HEADS, 256>>>();

    // 4) Output projection partials (128 blocks) + reduce -> out
    {
        dim3 grid(CDIM / 64, M_ROWS / 64, KSPLIT);
        gemm_splitk_kernel<<<grid, 256>>>(nullptr, W_proj, M_ROWS, CDIM, CDIM, 2);
        reduce_splitk_kernel<<<(M_ROWS * CDIM / 4 + 255) / 256, 256>>>(
            b_proj, out, CDIM, 2);
    }
}

// round 11
// speedup vs baseline: 1.5246x; 1.0216x over previous
#include <cuda_runtime.h>
#include <cuda_bf16.h>
#include <math.h>

// Problem constants
#define BATCH   16
#define HEADS   16
#define T_NEW   8
#define T_PAST  4096
#define T_FULL  4104
#define HD      64
#define CDIM    1024
#define M_ROWS  128          // B*T_new
#define QKV_N   3072

#define ATILE   128          // keys per tile
#define NSPLIT  4            // KV splits
#define SPAD    132          // S_s row stride
#define VPAD    72           // v_s row stride (halves at +0 / +36)
#define KSPLIT  4            // GEMM split-K factor

// Scratch (device globals; no allocations allowed)
__device__ float  g_qkv[M_ROWS * QKV_N];
__device__ float  g_y[M_ROWS * CDIM];
__device__ float  g_py[NSPLIT * 256 * T_NEW * HD];
__device__ float2 g_ml[NSPLIT * 256 * T_NEW];
__device__ float  g_gp[KSPLIT * M_ROWS * QKV_N];   // 6MB QKV split-K partials
__device__ float  g_pp[KSPLIT * M_ROWS * CDIM];    // 2MB proj split-K partials

// ---------------------------------------------------------------------------
// Split-K fp32 GEMM partial: P[z] = A[:, zK/S:(z+1)K/S] @ W[:, same]^T
// BM=BN=64, BK=16, 256 threads, 4x4 microtile.
// mode 1: A := Ap, P := g_gp.  mode 2: A := g_y, P := g_pp.
// ---------------------------------------------------------------------------
__global__ void __launch_bounds__(256) gemm_splitk_kernel(
    const float* __restrict__ Ap, const float* __restrict__ W,
    int M, int N, int K, int mode)
{
    const float* A = (mode == 2) ? g_y : Ap;
    float* P = (mode == 1) ? g_gp : g_pp;

    __shared__ float a_s[16][68];
    __shared__ float b_s[16][68];

    const int tid = threadIdx.x;
    const int m0 = blockIdx.y * 64;
    const int n0 = blockIdx.x * 64;
    const int kz = blockIdx.z;
    const int kchunk = K / KSPLIT;
    const int kbeg = kz * kchunk;

    const int tx = tid & 15;     // n sub (4 cols)
    const int ty = tid >> 4;     // m sub (4 rows)

    const int lr = tid >> 2;     // load row 0..63
    const int lc = tid & 3;      // load col-quad 0..3

    float acc[4][4];
#pragma unroll
    for (int i = 0; i < 4; i++)
#pragma unroll
        for (int j = 0; j < 4; j++) acc[i][j] = 0.f;

    for (int k0 = kbeg; k0 < kbeg + kchunk; k0 += 16) {
        {
            const float4 v = *(const float4*)&A[(size_t)(m0 + lr) * K + k0 + 4 * lc];
            a_s[4 * lc + 0][lr] = v.x; a_s[4 * lc + 1][lr] = v.y;
            a_s[4 * lc + 2][lr] = v.z; a_s[4 * lc + 3][lr] = v.w;
        }
        {
            const float4 v = *(const float4*)&W[(size_t)(n0 + lr) * K + k0 + 4 * lc];
            b_s[4 * lc + 0][lr] = v.x; b_s[4 * lc + 1][lr] = v.y;
            b_s[4 * lc + 2][lr] = v.z; b_s[4 * lc + 3][lr] = v.w;
        }
        __syncthreads();
#pragma unroll
        for (int kk = 0; kk < 16; kk++) {
            const float4 av = *(const float4*)&a_s[kk][ty * 4];
            const float4 bv = *(const float4*)&b_s[kk][tx * 4];
            const float am[4] = {av.x, av.y, av.z, av.w};
            const float bn[4] = {bv.x, bv.y, bv.z, bv.w};
#pragma unroll
            for (int i = 0; i < 4; i++)
#pragma unroll
                for (int j = 0; j < 4; j++) acc[i][j] += am[i] * bn[j];
        }
        __syncthreads();
    }

#pragma unroll
    for (int i = 0; i < 4; i++) {
        const size_t row = (size_t)kz * M + m0 + ty * 4 + i;
        *(float4*)&P[row * N + n0 + tx * 4] =
            make_float4(acc[i][0], acc[i][1], acc[i][2], acc[i][3]);
    }
}

// ---------------------------------------------------------------------------
// Reduce split-K partials + bias. One float4 per thread.
// ---------------------------------------------------------------------------
__global__ void __launch_bounds__(256) reduce_splitk_kernel(
    const float* __restrict__ bias, float* __restrict__ Cp, int N, int mode)
{
    const int idx = blockIdx.x * 256 + threadIdx.x;   // float4 index
    const float* P = (mode == 1) ? g_gp : g_pp;
    float* C = (mode == 1) ? g_qkv : Cp;
    const int total = M_ROWS * N / 4;
    if (idx >= total) return;

    const int col = (idx * 4) % N;
    float4 s = make_float4(0.f, 0.f, 0.f, 0.f);
#pragma unroll
    for (int z = 0; z < KSPLIT; z++) {
        const float4 v = *(const float4*)&P[(size_t)z * M_ROWS * N + idx * 4];
        s.x += v.x; s.y += v.y; s.z += v.z; s.w += v.w;
    }
    const float4 bb = *(const float4*)&bias[col];
    *(float4*)&C[(size_t)idx * 4] =
        make_float4(s.x + bb.x, s.y + bb.y, s.z + bb.z, s.w + bb.w);
}

// ---------------------------------------------------------------------------
// Fused attention + KV-cache copy, split-KV, coalesced, K-PREFETCH PIPELINE.
// Grid (256, 4). 256 threads, 8 warps. Warp w owns rows [16w,16w+16);
// instruction covers 2 rows (lane = 16B chunk, rh = row half): every
// LDG/STG.128 is 512B contiguous.
// Pipeline: kr holds tile t's K (loaded last iteration). Per tile:
//   V load+stores -> K copy-out -> scores(kr) -> PREFETCH K(t+1) -> sync
//   -> softmax -> sync -> PV -> sync -> kr = krn.
// K(t+1) LDG latency hides behind softmax+PV+barriers.
// ---------------------------------------------------------------------------
__global__ void __launch_bounds__(256, 2) attn_fused_kernel(
    const float* __restrict__ past_k, const float* __restrict__ past_v,
    float* __restrict__ out_k, float* __restrict__ out_v)
{
    __shared__ float q_s[T_NEW * HD];
    __shared__ float S_s[T_NEW * SPAD];
    __shared__ float v_s[ATILE * VPAD];   // row r: dims 0-31 at +0, 32-63 at +36
    __shared__ float f_s[T_NEW];

    const int bh = blockIdx.x;
    const int split = blockIdx.y;
    const int b = bh >> 4;
    const int h = bh & 15;
    const int tid = threadIdx.x;
    const int lane = tid & 31;
    const int w = tid >> 5;

    const int dg = lane & 15;    // 16B dim-chunk (dims 4dg..4dg+3)
    const int rh = lane >> 4;    // row half within instruction

    const int pqi = lane & 7;    // PV/score: query owned by this lane
    const int jg  = lane >> 3;   // PV: j subgroup
    const int voff = w * 8 + ((w >= 4) ? 4 : 0);

    // stage q to smem, then per-lane regs (dims 4dg..4dg+3 of each query)
    for (int idx = tid; idx < T_NEW * HD; idx += 256) {
        const int qq = idx >> 6, d = idx & 63;
        q_s[idx] = g_qkv[(size_t)(b * T_NEW + qq) * QKV_N + h * HD + d] * 0.125f;
    }
    __syncthreads();
    float4 qr[8];
#pragma unroll
    for (int qi = 0; qi < 8; qi++)
        qr[qi] = *(const float4*)&q_s[qi * HD + 4 * dg];

    float m = -INFINITY, l = 0.f;
    float acc[8];
#pragma unroll
    for (int d = 0; d < 8; d++) acc[d] = 0.f;

    const int tmax = (split == NSPLIT - 1) ? 9 : 8;

    // --- prologue: load K rows of tile 0 (always a full 128-key past tile) ---
    float4 kr[8];
#pragma unroll
    for (int i = 0; i < 8; i++) {
        const int r = 16 * w + 2 * i + rh;
        const int kt = split * 1024 + r;
        kr[i] = *(const float4*)(past_k + ((size_t)bh * T_PAST + kt) * HD + 4 * dg);
    }

    for (int t = 0; t < tmax; t++) {
        const int nk = (t < 8) ? ATILE : T_NEW;
        const int tilebase = split * 1024 + t * ATILE;

        // --- V: batched load (high MLP, coalesced 512B) ---
        float4 vr[8];
#pragma unroll
        for (int i = 0; i < 8; i++) {
            const int r = 16 * w + 2 * i + rh;
            const int kt = tilebase + r;
            if (r < nk) {
                const float* vs;
                if (kt < T_PAST) {
                    vs = past_v + ((size_t)bh * T_PAST + kt) * HD + 4 * dg;
                } else {
                    vs = g_qkv + (size_t)(b * T_NEW + (kt - T_PAST)) * QKV_N
                         + 2 * CDIM + h * HD + 4 * dg;
                }
                vr[i] = *(const float4*)vs;
            } else {
                vr[i] = make_float4(0.f, 0.f, 0.f, 0.f);
            }
        }
        // --- V copy-out + smem; K copy-out from kr ---
#pragma unroll
        for (int i = 0; i < 8; i++) {
            const int r = 16 * w + 2 * i + rh;
            const int kt = tilebase + r;
            if (r < nk) {
                __stcs((float4*)&out_v[((size_t)bh * T_FULL + kt) * HD + 4 * dg], vr[i]);
                *(float4*)&v_s[r * VPAD + 4 * dg + ((dg >= 8) ? 4 : 0)] = vr[i];
                __stcs((float4*)&out_k[((size_t)bh * T_FULL + kt) * HD + 4 * dg], kr[i]);
            }
        }

        // --- scores from kr: butterfly-fold over the 16 dim-lanes ---
#pragma unroll
        for (int i = 0; i < 8; i++) {
            float p[8];
#pragma unroll
            for (int qi = 0; qi < 8; qi++)
                p[qi] = qr[qi].x * kr[i].x + qr[qi].y * kr[i].y
                      + qr[qi].z * kr[i].z + qr[qi].w * kr[i].w;
#pragma unroll
            for (int qi = 0; qi < 8; qi++)
                p[qi] += __shfl_xor_sync(0xffffffffu, p[qi], 8);
#pragma unroll
            for (int q = 0; q < 4; q++) {
                const float send = (lane & 4) ? p[q] : p[q + 4];
                const float got = __shfl_xor_sync(0xffffffffu, send, 4);
                p[q] = ((lane & 4) ? p[q + 4] : p[q]) + got;
            }
#pragma unroll
            for (int q = 0; q < 2; q++) {
                const float send = (lane & 2) ? p[q] : p[q + 2];
                const float got = __shfl_xor_sync(0xffffffffu, send, 2);
                p[q] = ((lane & 2) ? p[q + 2] : p[q]) + got;
            }
            {
                const float send = (lane & 1) ? p[0] : p[1];
                const float got = __shfl_xor_sync(0xffffffffu, send, 1);
                p[0] = ((lane & 1) ? p[1] : p[0]) + got;
            }
            // lane holds s(row = 16w+2i+(lane>>4), qi = lane&7)
            if ((lane & 8) == 0) {
                const int r2 = 16 * w + 2 * i + (lane >> 4);
                const int kt2 = tilebase + r2;
                float sv = p[0];
                if (r2 >= nk) sv = -INFINITY;
                else if (kt2 >= T_PAST && pqi < (kt2 - T_PAST)) sv = -INFINITY;
                S_s[pqi * SPAD + r2] = sv;
            }
        }

        // --- PREFETCH K for tile t+1 (latency hides behind softmax+PV) ---
        float4 krn[8];
        if (t + 1 < tmax) {
            const int nk2 = (t + 1 < 8) ? ATILE : T_NEW;
            const int tb2 = split * 1024 + (t + 1) * ATILE;
#pragma unroll
            for (int i = 0; i < 8; i++) {
                const int r = 16 * w + 2 * i + rh;
                const int kt = tb2 + r;
                if (r < nk2) {
                    const float* ks;
                    if (kt < T_PAST) {
                        ks = past_k + ((size_t)bh * T_PAST + kt) * HD + 4 * dg;
                    } else {
                        ks = g_qkv + (size_t)(b * T_NEW + (kt - T_PAST)) * QKV_N
                             + CDIM + h * HD + 4 * dg;
                    }
                    krn[i] = *(const float4*)ks;
                } else {
                    krn[i] = make_float4(0.f, 0.f, 0.f, 0.f);
                }
            }
        } else {
#pragma unroll
            for (int i = 0; i < 8; i++)
                krn[i] = make_float4(0.f, 0.f, 0.f, 0.f);
        }
        __syncthreads();

        // --- online softmax: warp w owns query w ---
        float pr[4];
        float lmax = -INFINITY;
#pragma unroll
        for (int k = 0; k < 4; k++) {
            pr[k] = S_s[w * SPAD + lane + 32 * k];
            lmax = fmaxf(lmax, pr[k]);
        }
#pragma unroll
        for (int off = 16; off; off >>= 1)
            lmax = fmaxf(lmax, __shfl_xor_sync(0xffffffffu, lmax, off));
        const float m_new = fmaxf(m, lmax);
        const float factor = __expf(m - m_new);
        float psum = 0.f;
#pragma unroll
        for (int k = 0; k < 4; k++) {
            const float e = __expf(pr[k] - m_new);
            psum += e;
            S_s[w * SPAD + lane + 32 * k] = e;
        }
#pragma unroll
        for (int off = 16; off; off >>= 1)
            psum += __shfl_xor_sync(0xffffffffu, psum, off);
        l = l * factor + psum;
        m = m_new;
        if (lane == 0) f_s[w] = factor;
        __syncthreads();

        // --- PV: warp w covers dims [8w,8w+8); lane = (pqi, jg) ---
        {
            const float fct = f_s[pqi];
#pragma unroll
            for (int d = 0; d < 8; d++) acc[d] *= fct;
            const float* vrow = v_s + voff;
#pragma unroll 4
            for (int jb = 0; jb < 32; jb++) {
                const int j = jb * 4 + jg;
                const float p = S_s[pqi * SPAD + j];
                const float4 va = *(const float4*)&vrow[j * VPAD];
                const float4 vb = *(const float4*)&vrow[j * VPAD + 4];
                acc[0] += p * va.x; acc[1] += p * va.y;
                acc[2] += p * va.z; acc[3] += p * va.w;
                acc[4] += p * vb.x; acc[5] += p * vb.y;
                acc[6] += p * vb.z; acc[7] += p * vb.w;
            }
        }
        __syncthreads();

        // rotate pipeline
#pragma unroll
        for (int i = 0; i < 8; i++) kr[i] = krn[i];
    }

    // reduce over jg (xor 8, 16) — warp-uniform
#pragma unroll
    for (int d = 0; d < 8; d++) {
        acc[d] += __shfl_xor_sync(0xffffffffu, acc[d], 8);
        acc[d] += __shfl_xor_sync(0xffffffffu, acc[d], 16);
    }
    if (lane < 8) {
        const size_t base = ((size_t)(split * 256 + bh) * T_NEW + lane) * HD + w * 8;
        *(float4*)&g_py[base]     = make_float4(acc[0], acc[1], acc[2], acc[3]);
        *(float4*)&g_py[base + 4] = make_float4(acc[4], acc[5], acc[6], acc[7]);
    }
    if (lane == 0)
        g_ml[(split * 256 + bh) * T_NEW + w] = make_float2(m, l);
}

// ---------------------------------------------------------------------------
// Combine split partials -> g_y. Grid 256 (bh), 256 threads.
// ---------------------------------------------------------------------------
__global__ void __launch_bounds__(256) combine_kernel()
{
    const int bh = blockIdx.x;
    const int b = bh >> 4;
    const int h = bh & 15;
    const int tid = threadIdx.x;
    const int qi = tid >> 5;
    const int dd = (tid & 31) * 2;

    float2 ml[NSPLIT];
    float M = -INFINITY;
#pragma unroll
    for (int s = 0; s < NSPLIT; s++) {
        ml[s] = g_ml[(s * 256 + bh) * T_NEW + qi];
        M = fmaxf(M, ml[s].x);
    }
    float lt = 0.f, y0 = 0.f, y1 = 0.f;
#pragma unroll
    for (int s = 0; s < NSPLIT; s++) {
        const float wt = __expf(ml[s].x - M);
        lt += ml[s].y * wt;
        const float2 yv = *(const float2*)
            &g_py[((size_t)(s * 256 + bh) * T_NEW + qi) * HD + dd];
        y0 += yv.x * wt;
        y1 += yv.y * wt;
    }
    const float inv = 1.f / lt;
    *(float2*)&g_y[(size_t)(b * T_NEW + qi) * CDIM + h * HD + dd] =
        make_float2(y0 * inv, y1 * inv);
}

// ---------------------------------------------------------------------------
// Launcher — ONLY kernel launches.
// Output layout: [ out (128*1024) | k (256*4104*64) | v (256*4104*64) ]
// ---------------------------------------------------------------------------
extern "C" void kernel_launch(void* const* d_in, const int* in_sizes, int n_in,
                              void* d_out, int out_size)
{
    const float* x      = (const float*)d_in[0];
    const float* past_k = (const float*)d_in[1];
    const float* past_v = (const float*)d_in[2];
    const float* W_attn = (const float*)d_in[3];
    const float* b_attn = (const float*)d_in[4];
    const float* W_proj = (const float*)d_in[5];
    const float* b_proj = (const float*)d_in[6];

    float* out   = (float*)d_out;
    float* out_k = out + (size_t)M_ROWS * CDIM;
    float* out_v = out_k + (size_t)BATCH * HEADS * T_FULL * HD;

    // 1) QKV projection partials (384 blocks) + reduce -> g_qkv
    {
        dim3 grid(QKV_N / 64, M_ROWS / 64, KSPLIT);
        gemm_splitk_kernel<<<grid, 256>>>(x, W_attn, M_ROWS, QKV_N, CDIM, 1);
        reduce_splitk_kernel<<<(M_ROWS * QKV_N / 4 + 255) / 256, 256>>>(
            b_attn, nullptr, QKV_N, 1);
    }

    // 2) Fused attention + KV-cache copy (split-KV, 1024 blocks)
    {
        dim3 grid(BATCH * HEADS, NSPLIT);
        attn_fused_kernel<<<grid, 256>>>(past_k, past_v, out_k, out_v);
    }

    // 3) Combine split partials -> g_y
    combine_kernel<<<BATCH * HEADS, 256>>>();

    // 4) Output projection partials (128 blocks) + reduce -> out
    {
        dim3 grid(CDIM / 64, M_ROWS / 64, KSPLIT);
        gemm_splitk_kernel<<<grid, 256>>>(nullptr, W_proj, M_ROWS, CDIM, CDIM, 2);
        reduce_splitk_kernel<<<(M_ROWS * CDIM / 4 + 255) / 256, 256>>>(
            b_proj, out, CDIM, 2);
    }
}